// round 3
// baseline (speedup 1.0000x reference)
#include <cuda_runtime.h>

#define B_ 256
#define S_ 197
#define D_ 768
#define D4_ 192
#define P_ 20
#define L_ 5
#define T_ 10
#define K_ 5
#define ROWS_TOK 75            // (T+K)*L
#define ROWS_PE 272            // ROWS_TOK + S

// float offsets into d_out
#define PE_OFF   0ULL
#define SIM_OFF  53477376ULL
#define TOK_OFF  53477377ULL
#define IDX_OFF  68222977ULL
#define XN_OFF   68224257ULL

// scratch (device globals; no allocations)
__device__ float g_part[4 * B_ * D_];
__device__ float g_xnorm[B_ * D_];
__device__ float g_pnorm[P_ * D_];
__device__ int   g_idx[B_ * K_];
__device__ int   g_cnt[P_];

// 192-thread block reduce (padded to 256 in shared)
__device__ __forceinline__ float blk_reduce_192(float v) {
    __shared__ float sh[256];
    int t = threadIdx.x;
    sh[t] = v;
    if (t < 64) sh[192 + t] = 0.f;
    __syncthreads();
    for (int s = 128; s > 0; s >>= 1) {
        if (t < s) sh[t] += sh[t + s];
        __syncthreads();
    }
    return sh[0];
}

// ---------------------------------------------------------------------------
// Kernel 1: grid (B, 5), block 192.
//  q<4 : stream x_embed -> prompted_embedding[:, 75:, :] + 4-way partial sums.
//  q==4: b<P -> l2-normalize prompt_key row b; (b==0) zero g_cnt.
// ---------------------------------------------------------------------------
__global__ void k_mean_copy(const float4* __restrict__ x,
                            const float4* __restrict__ pk,
                            float* __restrict__ out) {
    int b = blockIdx.x;
    int q = blockIdx.y;
    int t = threadIdx.x;                 // 0..191

    if (q == 4) {
        if (b == 0 && t < P_) g_cnt[t] = 0;
        if (b >= P_) return;
        float4 v = pk[(size_t)b * D4_ + t];
        float ss = blk_reduce_192(v.x * v.x + v.y * v.y + v.z * v.z + v.w * v.w);
        float r = rsqrtf(fmaxf(ss, 1e-12f));
        float4 n = make_float4(v.x * r, v.y * r, v.z * r, v.w * r);
        ((float4*)g_pnorm)[(size_t)b * D4_ + t] = n;
        return;
    }

    int s0 = q * 50;
    int s1 = (q == 3) ? S_ : s0 + 50;

    const float4* xb = x + (size_t)b * S_ * D4_;
    float4* ob = ((float4*)(out + PE_OFF)) + (size_t)b * ROWS_PE * D4_ + (size_t)ROWS_TOK * D4_;

    float4 acc = make_float4(0.f, 0.f, 0.f, 0.f);
    for (int s = s0; s < s1; s++) {
        float4 v = xb[(size_t)s * D4_ + t];
        acc.x += v.x; acc.y += v.y; acc.z += v.z; acc.w += v.w;
        ob[(size_t)s * D4_ + t] = v;
    }
    ((float4*)g_part)[(size_t)q * B_ * D4_ + (size_t)b * D4_ + t] = acc;
}

// ---------------------------------------------------------------------------
// Kernel 2: grid B, block 192. Combine partials -> mean -> l2-normalize;
// write x_norm (out + scratch); then 20 similarity dots (6 warps, shared x)
// and top-5 / idx_pruned / counts — all in one block per b.
// ---------------------------------------------------------------------------
__global__ void k_xnorm_topk(float* __restrict__ out) {
    __shared__ float  sh[256];
    __shared__ float4 shx[D4_];
    __shared__ float  shsim[P_];
    int b = blockIdx.x;
    int t = threadIdx.x;

    const float4* part = (const float4*)g_part;
    float4 a  = part[(size_t)0 * B_ * D4_ + (size_t)b * D4_ + t];
    float4 c1 = part[(size_t)1 * B_ * D4_ + (size_t)b * D4_ + t];
    float4 c2 = part[(size_t)2 * B_ * D4_ + (size_t)b * D4_ + t];
    float4 c3 = part[(size_t)3 * B_ * D4_ + (size_t)b * D4_ + t];
    const float inv = 1.0f / (float)S_;
    a.x = (a.x + c1.x + c2.x + c3.x) * inv;
    a.y = (a.y + c1.y + c2.y + c3.y) * inv;
    a.z = (a.z + c1.z + c2.z + c3.z) * inv;
    a.w = (a.w + c1.w + c2.w + c3.w) * inv;

    // block reduce of squared sum
    sh[t] = a.x * a.x + a.y * a.y + a.z * a.z + a.w * a.w;
    if (t < 64) sh[192 + t] = 0.f;
    __syncthreads();
    for (int s = 128; s > 0; s >>= 1) {
        if (t < s) sh[t] += sh[t + s];
        __syncthreads();
    }
    float r = rsqrtf(fmaxf(sh[0], 1e-12f));
    float4 n = make_float4(a.x * r, a.y * r, a.z * r, a.w * r);

    ((float4*)g_xnorm)[(size_t)b * D4_ + t] = n;
    float* xo = out + XN_OFF + (size_t)b * D_ + (size_t)t * 4;
    xo[0] = n.x; xo[1] = n.y; xo[2] = n.z; xo[3] = n.w;

    // stage x row for similarity dots
    shx[t] = n;
    __syncthreads();

    int w = t >> 5;          // 0..5
    int lane = t & 31;
    for (int p = w; p < P_; p += 6) {
        const float4* pn = ((const float4*)g_pnorm) + (size_t)p * D4_;
        float acc = 0.f;
#pragma unroll
        for (int i = 0; i < 6; i++) {
            int j = lane + 32 * i;
            float4 pv = pn[j];
            float4 xv = shx[j];
            acc += xv.x * pv.x + xv.y * pv.y + xv.z * pv.z + xv.w * pv.w;
        }
#pragma unroll
        for (int off = 16; off > 0; off >>= 1)
            acc += __shfl_down_sync(0xffffffffu, acc, off);
        if (lane == 0) shsim[p] = acc;
    }
    __syncthreads();

    if (t == 0) {
        float sim[P_];
        bool used[P_];
#pragma unroll
        for (int p = 0; p < P_; p++) { sim[p] = shsim[p]; used[p] = false; }
        for (int k = 0; k < K_; k++) {
            float best = -3.4e38f;
            int bi = 0;
#pragma unroll
            for (int p = 0; p < P_; p++) {
                if (!used[p] && sim[p] > best) { best = sim[p]; bi = p; }
            }
            used[bi] = true;
            bool keep = best > 0.0f;
            int idxp = keep ? bi : -1;
            g_idx[b * K_ + k] = idxp;
            out[IDX_OFF + (size_t)b * K_ + k] = (float)idxp;
            if (keep) atomicAdd(&g_cnt[bi], 1);
        }
    }
}

// ---------------------------------------------------------------------------
// Kernel 3: grid (76, B), block 192.
//  r<75      : token row -> prompted_embedding[:, :75, :] AND tokens output.
//  r==75,b==0: reduce_sim = dot(sum_b x_norm, sum_p cnt[p]*p_norm[p]) / B.
// ---------------------------------------------------------------------------
__global__ void k_tokens(const float4* __restrict__ prompt,
                         const float4* __restrict__ assist,
                         float* __restrict__ out) {
    int r = blockIdx.x;      // 0..75
    int b = blockIdx.y;
    int t = threadIdx.x;     // 0..191

    if (r == ROWS_TOK) {
        if (b != 0) return;
        // reduce_sim: each thread covers d = 4t..4t+3
        float4 sx = make_float4(0.f, 0.f, 0.f, 0.f);
        const float4* xn = (const float4*)g_xnorm;
#pragma unroll 4
        for (int bb = 0; bb < B_; bb++) {
            float4 v = xn[(size_t)bb * D4_ + t];
            sx.x += v.x; sx.y += v.y; sx.z += v.z; sx.w += v.w;
        }
        float4 kt = make_float4(0.f, 0.f, 0.f, 0.f);
#pragma unroll
        for (int p = 0; p < P_; p++) {
            float c = (float)g_cnt[p];
            float4 v = ((const float4*)g_pnorm)[(size_t)p * D4_ + t];
            kt.x += c * v.x; kt.y += c * v.y; kt.z += c * v.z; kt.w += c * v.w;
        }
        float partial = sx.x * kt.x + sx.y * kt.y + sx.z * kt.z + sx.w * kt.w;
        float tot = blk_reduce_192(partial);
        if (t == 0) out[SIM_OFF] = tot * (1.0f / (float)B_);
        return;
    }

    float4 v;
    if (r < T_ * L_) {
        v = assist[(size_t)r * D4_ + t];
    } else {
        int rr = r - T_ * L_;
        int k = rr / L_;
        int l = rr % L_;
        int idx = g_idx[b * K_ + k];
        if (idx >= 0)
            v = prompt[((size_t)idx * L_ + l) * D4_ + t];
        else
            v = make_float4(0.f, 0.f, 0.f, 0.f);
    }
    ((float4*)(out + PE_OFF))[(size_t)b * ROWS_PE * D4_ + (size_t)r * D4_ + t] = v;
    float* to = out + TOK_OFF + (size_t)b * ROWS_TOK * D_ + (size_t)r * D_ + (size_t)t * 4;
    to[0] = v.x; to[1] = v.y; to[2] = v.z; to[3] = v.w;
}

extern "C" void kernel_launch(void* const* d_in, const int* in_sizes, int n_in,
                              void* d_out, int out_size) {
    const float4* x_embed = (const float4*)d_in[0];        // [B,S,D]
    const float4* prompt = (const float4*)d_in[1];         // [P,L,D]
    const float4* prompt_key = (const float4*)d_in[2];     // [P,D]
    const float4* assist = (const float4*)d_in[3];         // [T,L,D]
    float* out = (float*)d_out;

    k_mean_copy<<<dim3(B_, 5), D4_>>>(x_embed, prompt_key, out);
    k_xnorm_topk<<<B_, D4_>>>(out);
    k_tokens<<<dim3(ROWS_TOK + 1, B_), D4_>>>(prompt, assist, out);
}

// round 4
// speedup vs baseline: 1.2301x; 1.2301x over previous
#include <cuda_runtime.h>

#define B_ 256
#define S_ 197
#define D_ 768
#define D4_ 192
#define P_ 20
#define L_ 5
#define T_ 10
#define K_ 5
#define ROWS_TOK 75            // (T+K)*L
#define ROWS_PE 272            // ROWS_TOK + S

// float offsets into d_out
#define PE_OFF   0ULL
#define SIM_OFF  53477376ULL
#define TOK_OFF  53477377ULL
#define IDX_OFF  68222977ULL
#define XN_OFF   68224257ULL

// scratch (device globals; no allocations)
__device__ float g_part[4 * B_ * D_];
__device__ float g_xnorm[B_ * D_];
__device__ float g_pnorm[P_ * D_];
__device__ int   g_idx[B_ * K_];
__device__ int   g_cnt[P_];

// 192-thread block reduce (padded to 256 in shared)
__device__ __forceinline__ float blk_reduce_192(float v) {
    __shared__ float sh[256];
    int t = threadIdx.x;
    sh[t] = v;
    if (t < 64) sh[192 + t] = 0.f;
    __syncthreads();
    for (int s = 128; s > 0; s >>= 1) {
        if (t < s) sh[t] += sh[t + s];
        __syncthreads();
    }
    return sh[0];
}

// ---------------------------------------------------------------------------
// Kernel 1: grid (B, 5), block 192.
//  q<4 : stream x_embed -> prompted_embedding[:, 75:, :] + 4-way partial sums.
//        Unrolled x5 (load batch then store batch) for MLP; streaming hints.
//  q==4: b<P -> l2-normalize prompt_key row b; (b==0) zero g_cnt.
// ---------------------------------------------------------------------------
__global__ void k_mean_copy(const float4* __restrict__ x,
                            const float4* __restrict__ pk,
                            float* __restrict__ out) {
    int b = blockIdx.x;
    int q = blockIdx.y;
    int t = threadIdx.x;                 // 0..191

    if (q == 4) {
        if (b == 0 && t < P_) g_cnt[t] = 0;
        if (b >= P_) return;
        float4 v = pk[(size_t)b * D4_ + t];
        float ss = blk_reduce_192(v.x * v.x + v.y * v.y + v.z * v.z + v.w * v.w);
        float r = rsqrtf(fmaxf(ss, 1e-12f));
        float4 n = make_float4(v.x * r, v.y * r, v.z * r, v.w * r);
        ((float4*)g_pnorm)[(size_t)b * D4_ + t] = n;
        return;
    }

    int s0 = q * 50;
    int s1 = (q == 3) ? S_ : s0 + 50;

    const float4* xb = x + (size_t)b * S_ * D4_ + t;
    float4* ob = ((float4*)(out + PE_OFF)) + (size_t)b * ROWS_PE * D4_ + (size_t)ROWS_TOK * D4_ + t;

    float4 acc = make_float4(0.f, 0.f, 0.f, 0.f);
    int s = s0;
    for (; s + 5 <= s1; s += 5) {
        float4 v0 = __ldcs(xb + (size_t)(s + 0) * D4_);
        float4 v1 = __ldcs(xb + (size_t)(s + 1) * D4_);
        float4 v2 = __ldcs(xb + (size_t)(s + 2) * D4_);
        float4 v3 = __ldcs(xb + (size_t)(s + 3) * D4_);
        float4 v4 = __ldcs(xb + (size_t)(s + 4) * D4_);
        acc.x += v0.x + v1.x + v2.x + v3.x + v4.x;
        acc.y += v0.y + v1.y + v2.y + v3.y + v4.y;
        acc.z += v0.z + v1.z + v2.z + v3.z + v4.z;
        acc.w += v0.w + v1.w + v2.w + v3.w + v4.w;
        __stcs(ob + (size_t)(s + 0) * D4_, v0);
        __stcs(ob + (size_t)(s + 1) * D4_, v1);
        __stcs(ob + (size_t)(s + 2) * D4_, v2);
        __stcs(ob + (size_t)(s + 3) * D4_, v3);
        __stcs(ob + (size_t)(s + 4) * D4_, v4);
    }
    for (; s < s1; s++) {
        float4 v = __ldcs(xb + (size_t)s * D4_);
        acc.x += v.x; acc.y += v.y; acc.z += v.z; acc.w += v.w;
        __stcs(ob + (size_t)s * D4_, v);
    }
    ((float4*)g_part)[(size_t)q * B_ * D4_ + (size_t)b * D4_ + t] = acc;
}

// ---------------------------------------------------------------------------
// Kernel 2: grid B, block 192. Combine partials -> mean -> l2-normalize;
// write x_norm (out + scratch); then 20 similarity dots (6 warps, shared x)
// and top-5 / idx_pruned / counts — all in one block per b.
// ---------------------------------------------------------------------------
__global__ void k_xnorm_topk(float* __restrict__ out) {
    __shared__ float  sh[256];
    __shared__ float4 shx[D4_];
    __shared__ float  shsim[P_];
    int b = blockIdx.x;
    int t = threadIdx.x;

    const float4* part = (const float4*)g_part;
    float4 a  = part[(size_t)0 * B_ * D4_ + (size_t)b * D4_ + t];
    float4 c1 = part[(size_t)1 * B_ * D4_ + (size_t)b * D4_ + t];
    float4 c2 = part[(size_t)2 * B_ * D4_ + (size_t)b * D4_ + t];
    float4 c3 = part[(size_t)3 * B_ * D4_ + (size_t)b * D4_ + t];
    const float inv = 1.0f / (float)S_;
    a.x = (a.x + c1.x + c2.x + c3.x) * inv;
    a.y = (a.y + c1.y + c2.y + c3.y) * inv;
    a.z = (a.z + c1.z + c2.z + c3.z) * inv;
    a.w = (a.w + c1.w + c2.w + c3.w) * inv;

    // block reduce of squared sum
    sh[t] = a.x * a.x + a.y * a.y + a.z * a.z + a.w * a.w;
    if (t < 64) sh[192 + t] = 0.f;
    __syncthreads();
    for (int s = 128; s > 0; s >>= 1) {
        if (t < s) sh[t] += sh[t + s];
        __syncthreads();
    }
    float r = rsqrtf(fmaxf(sh[0], 1e-12f));
    float4 n = make_float4(a.x * r, a.y * r, a.z * r, a.w * r);

    ((float4*)g_xnorm)[(size_t)b * D4_ + t] = n;
    float* xo = out + XN_OFF + (size_t)b * D_ + (size_t)t * 4;
    xo[0] = n.x; xo[1] = n.y; xo[2] = n.z; xo[3] = n.w;

    // stage x row for similarity dots
    shx[t] = n;
    __syncthreads();

    int w = t >> 5;          // 0..5
    int lane = t & 31;
    for (int p = w; p < P_; p += 6) {
        const float4* pn = ((const float4*)g_pnorm) + (size_t)p * D4_;
        float acc = 0.f;
#pragma unroll
        for (int i = 0; i < 6; i++) {
            int j = lane + 32 * i;
            float4 pv = pn[j];
            float4 xv = shx[j];
            acc += xv.x * pv.x + xv.y * pv.y + xv.z * pv.z + xv.w * pv.w;
        }
#pragma unroll
        for (int off = 16; off > 0; off >>= 1)
            acc += __shfl_down_sync(0xffffffffu, acc, off);
        if (lane == 0) shsim[p] = acc;
    }
    __syncthreads();

    if (t == 0) {
        float sim[P_];
        bool used[P_];
#pragma unroll
        for (int p = 0; p < P_; p++) { sim[p] = shsim[p]; used[p] = false; }
        for (int k = 0; k < K_; k++) {
            float best = -3.4e38f;
            int bi = 0;
#pragma unroll
            for (int p = 0; p < P_; p++) {
                if (!used[p] && sim[p] > best) { best = sim[p]; bi = p; }
            }
            used[bi] = true;
            bool keep = best > 0.0f;
            int idxp = keep ? bi : -1;
            g_idx[b * K_ + k] = idxp;
            out[IDX_OFF + (size_t)b * K_ + k] = (float)idxp;
            if (keep) atomicAdd(&g_cnt[bi], 1);
        }
    }
}

// ---------------------------------------------------------------------------
// Kernel 3: grid (76, B), block 192.
//  r<75      : token row -> prompted_embedding[:, :75, :] AND tokens output.
//  r==75,b==0: reduce_sim = dot(sum_b x_norm, sum_p cnt[p]*p_norm[p]) / B.
// ---------------------------------------------------------------------------
__global__ void k_tokens(const float4* __restrict__ prompt,
                         const float4* __restrict__ assist,
                         float* __restrict__ out) {
    int r = blockIdx.x;      // 0..75
    int b = blockIdx.y;
    int t = threadIdx.x;     // 0..191

    if (r == ROWS_TOK) {
        if (b != 0) return;
        // reduce_sim: each thread covers d = 4t..4t+3; unroll x8 for MLP
        float4 sx = make_float4(0.f, 0.f, 0.f, 0.f);
        const float4* xn = (const float4*)g_xnorm + t;
#pragma unroll
        for (int bb = 0; bb < B_; bb += 8) {
            float4 v0 = xn[(size_t)(bb + 0) * D4_];
            float4 v1 = xn[(size_t)(bb + 1) * D4_];
            float4 v2 = xn[(size_t)(bb + 2) * D4_];
            float4 v3 = xn[(size_t)(bb + 3) * D4_];
            float4 v4 = xn[(size_t)(bb + 4) * D4_];
            float4 v5 = xn[(size_t)(bb + 5) * D4_];
            float4 v6 = xn[(size_t)(bb + 6) * D4_];
            float4 v7 = xn[(size_t)(bb + 7) * D4_];
            sx.x += (v0.x + v1.x) + (v2.x + v3.x) + ((v4.x + v5.x) + (v6.x + v7.x));
            sx.y += (v0.y + v1.y) + (v2.y + v3.y) + ((v4.y + v5.y) + (v6.y + v7.y));
            sx.z += (v0.z + v1.z) + (v2.z + v3.z) + ((v4.z + v5.z) + (v6.z + v7.z));
            sx.w += (v0.w + v1.w) + (v2.w + v3.w) + ((v4.w + v5.w) + (v6.w + v7.w));
        }
        float4 kt = make_float4(0.f, 0.f, 0.f, 0.f);
#pragma unroll
        for (int p = 0; p < P_; p++) {
            float c = (float)g_cnt[p];
            float4 v = ((const float4*)g_pnorm)[(size_t)p * D4_ + t];
            kt.x += c * v.x; kt.y += c * v.y; kt.z += c * v.z; kt.w += c * v.w;
        }
        float partial = sx.x * kt.x + sx.y * kt.y + sx.z * kt.z + sx.w * kt.w;
        float tot = blk_reduce_192(partial);
        if (t == 0) out[SIM_OFF] = tot * (1.0f / (float)B_);
        return;
    }

    float4 v;
    if (r < T_ * L_) {
        v = assist[(size_t)r * D4_ + t];
    } else {
        int rr = r - T_ * L_;
        int k = rr / L_;
        int l = rr % L_;
        int idx = g_idx[b * K_ + k];
        if (idx >= 0)
            v = prompt[((size_t)idx * L_ + l) * D4_ + t];
        else
            v = make_float4(0.f, 0.f, 0.f, 0.f);
    }
    __stcs((float4*)(out + PE_OFF) + (size_t)b * ROWS_PE * D4_ + (size_t)r * D4_ + t, v);
    float* to = out + TOK_OFF + (size_t)b * ROWS_TOK * D_ + (size_t)r * D_ + (size_t)t * 4;
    __stcs(to + 0, v.x);
    __stcs(to + 1, v.y);
    __stcs(to + 2, v.z);
    __stcs(to + 3, v.w);
}

extern "C" void kernel_launch(void* const* d_in, const int* in_sizes, int n_in,
                              void* d_out, int out_size) {
    const float4* x_embed = (const float4*)d_in[0];        // [B,S,D]
    const float4* prompt = (const float4*)d_in[1];         // [P,L,D]
    const float4* prompt_key = (const float4*)d_in[2];     // [P,D]
    const float4* assist = (const float4*)d_in[3];         // [T,L,D]
    float* out = (float*)d_out;

    k_mean_copy<<<dim3(B_, 5), D4_>>>(x_embed, prompt_key, out);
    k_xnorm_topk<<<B_, D4_>>>(out);
    k_tokens<<<dim3(ROWS_TOK + 1, B_), D4_>>>(prompt, assist, out);
}

// round 5
// speedup vs baseline: 1.3161x; 1.0699x over previous
#include <cuda_runtime.h>

#define B_ 256
#define S_ 197
#define D_ 768
#define D4_ 192
#define P_ 20
#define L_ 5
#define T_ 10
#define K_ 5
#define ROWS_TOK 75            // (T+K)*L
#define ROWS_PE 272            // ROWS_TOK + S
#define Q_ 8                   // mean/copy chunks per batch row
#define CHUNK 25               // rows per chunk (last chunk = 22)

// float offsets into d_out
#define PE_OFF   0ULL
#define SIM_OFF  53477376ULL
#define TOK_OFF  53477377ULL
#define IDX_OFF  68222977ULL
#define XN_OFF   68224257ULL

// scratch (device globals; no allocations)
__device__ float g_part[Q_ * B_ * D_];
__device__ float g_xnorm[B_ * D_];
__device__ float g_pnorm[P_ * D_];
__device__ int   g_idx[B_ * K_];
__device__ int   g_cnt[P_];

// 192-thread block reduce (padded to 256 in shared)
__device__ __forceinline__ float blk_reduce_192(float v) {
    __shared__ float sh[256];
    int t = threadIdx.x;
    sh[t] = v;
    if (t < 64) sh[192 + t] = 0.f;
    __syncthreads();
    for (int s = 128; s > 0; s >>= 1) {
        if (t < s) sh[t] += sh[t + s];
        __syncthreads();
    }
    return sh[0];
}

// ---------------------------------------------------------------------------
// Kernel 1: grid (B, Q_+1), block 192.
//  q<Q_ : stream x_embed rows [q*25, ...) -> prompted_embedding[:, 75:, :]
//         + partial sums. Unrolled x5 for MLP; streaming hints.
//  q==Q_: b<P -> l2-normalize prompt_key row b; (b==0) zero g_cnt.
// ---------------------------------------------------------------------------
__global__ void k_mean_copy(const float4* __restrict__ x,
                            const float4* __restrict__ pk,
                            float* __restrict__ out) {
    int b = blockIdx.x;
    int q = blockIdx.y;
    int t = threadIdx.x;                 // 0..191

    if (q == Q_) {
        if (b == 0 && t < P_) g_cnt[t] = 0;
        if (b >= P_) return;
        float4 v = pk[(size_t)b * D4_ + t];
        float ss = blk_reduce_192(v.x * v.x + v.y * v.y + v.z * v.z + v.w * v.w);
        float r = rsqrtf(fmaxf(ss, 1e-12f));
        float4 n = make_float4(v.x * r, v.y * r, v.z * r, v.w * r);
        ((float4*)g_pnorm)[(size_t)b * D4_ + t] = n;
        return;
    }

    int s0 = q * CHUNK;
    int s1 = (q == Q_ - 1) ? S_ : s0 + CHUNK;

    const float4* xb = x + (size_t)b * S_ * D4_ + t;
    float4* ob = ((float4*)(out + PE_OFF)) + (size_t)b * ROWS_PE * D4_ + (size_t)ROWS_TOK * D4_ + t;

    float4 acc = make_float4(0.f, 0.f, 0.f, 0.f);
    int s = s0;
    for (; s + 5 <= s1; s += 5) {
        float4 v0 = __ldcs(xb + (size_t)(s + 0) * D4_);
        float4 v1 = __ldcs(xb + (size_t)(s + 1) * D4_);
        float4 v2 = __ldcs(xb + (size_t)(s + 2) * D4_);
        float4 v3 = __ldcs(xb + (size_t)(s + 3) * D4_);
        float4 v4 = __ldcs(xb + (size_t)(s + 4) * D4_);
        acc.x += v0.x + v1.x + v2.x + v3.x + v4.x;
        acc.y += v0.y + v1.y + v2.y + v3.y + v4.y;
        acc.z += v0.z + v1.z + v2.z + v3.z + v4.z;
        acc.w += v0.w + v1.w + v2.w + v3.w + v4.w;
        __stcs(ob + (size_t)(s + 0) * D4_, v0);
        __stcs(ob + (size_t)(s + 1) * D4_, v1);
        __stcs(ob + (size_t)(s + 2) * D4_, v2);
        __stcs(ob + (size_t)(s + 3) * D4_, v3);
        __stcs(ob + (size_t)(s + 4) * D4_, v4);
    }
    for (; s < s1; s++) {
        float4 v = __ldcs(xb + (size_t)s * D4_);
        acc.x += v.x; acc.y += v.y; acc.z += v.z; acc.w += v.w;
        __stcs(ob + (size_t)s * D4_, v);
    }
    ((float4*)g_part)[(size_t)q * B_ * D4_ + (size_t)b * D4_ + t] = acc;
}

// ---------------------------------------------------------------------------
// Kernel 2: grid B, block 192. Combine Q_ partials -> mean -> l2-normalize;
// write x_norm (out + scratch); then 20 similarity dots (6 warps, shared x)
// and top-5 / idx_pruned / counts — all in one block per b.
// ---------------------------------------------------------------------------
__global__ void k_xnorm_topk(float* __restrict__ out) {
    __shared__ float  sh[256];
    __shared__ float4 shx[D4_];
    __shared__ float  shsim[P_];
    int b = blockIdx.x;
    int t = threadIdx.x;

    const float4* part = (const float4*)g_part + (size_t)b * D4_ + t;
    float4 a = make_float4(0.f, 0.f, 0.f, 0.f);
#pragma unroll
    for (int q = 0; q < Q_; q++) {
        float4 c = part[(size_t)q * B_ * D4_];
        a.x += c.x; a.y += c.y; a.z += c.z; a.w += c.w;
    }
    const float inv = 1.0f / (float)S_;
    a.x *= inv; a.y *= inv; a.z *= inv; a.w *= inv;

    // block reduce of squared sum
    sh[t] = a.x * a.x + a.y * a.y + a.z * a.z + a.w * a.w;
    if (t < 64) sh[192 + t] = 0.f;
    __syncthreads();
    for (int s = 128; s > 0; s >>= 1) {
        if (t < s) sh[t] += sh[t + s];
        __syncthreads();
    }
    float r = rsqrtf(fmaxf(sh[0], 1e-12f));
    float4 n = make_float4(a.x * r, a.y * r, a.z * r, a.w * r);

    ((float4*)g_xnorm)[(size_t)b * D4_ + t] = n;
    float* xo = out + XN_OFF + (size_t)b * D_ + (size_t)t * 4;
    xo[0] = n.x; xo[1] = n.y; xo[2] = n.z; xo[3] = n.w;

    // stage x row for similarity dots
    shx[t] = n;
    __syncthreads();

    int w = t >> 5;          // 0..5
    int lane = t & 31;
    for (int p = w; p < P_; p += 6) {
        const float4* pn = ((const float4*)g_pnorm) + (size_t)p * D4_;
        float acc = 0.f;
#pragma unroll
        for (int i = 0; i < 6; i++) {
            int j = lane + 32 * i;
            float4 pv = pn[j];
            float4 xv = shx[j];
            acc += xv.x * pv.x + xv.y * pv.y + xv.z * pv.z + xv.w * pv.w;
        }
#pragma unroll
        for (int off = 16; off > 0; off >>= 1)
            acc += __shfl_down_sync(0xffffffffu, acc, off);
        if (lane == 0) shsim[p] = acc;
    }
    __syncthreads();

    if (t == 0) {
        float sim[P_];
        bool used[P_];
#pragma unroll
        for (int p = 0; p < P_; p++) { sim[p] = shsim[p]; used[p] = false; }
        for (int k = 0; k < K_; k++) {
            float best = -3.4e38f;
            int bi = 0;
#pragma unroll
            for (int p = 0; p < P_; p++) {
                if (!used[p] && sim[p] > best) { best = sim[p]; bi = p; }
            }
            used[bi] = true;
            bool keep = best > 0.0f;
            int idxp = keep ? bi : -1;
            g_idx[b * K_ + k] = idxp;
            out[IDX_OFF + (size_t)b * K_ + k] = (float)idxp;
            if (keep) atomicAdd(&g_cnt[bi], 1);
        }
    }
}

// ---------------------------------------------------------------------------
// Kernel 3: grid (76, B), block 192.
//  r<75      : token row -> prompted_embedding[:, :75, :] AND tokens output.
//  r==75,b==0: reduce_sim = dot(sum_b x_norm, sum_p cnt[p]*p_norm[p]) / B.
// ---------------------------------------------------------------------------
__global__ void k_tokens(const float4* __restrict__ prompt,
                         const float4* __restrict__ assist,
                         float* __restrict__ out) {
    int r = blockIdx.x;      // 0..75
    int b = blockIdx.y;
    int t = threadIdx.x;     // 0..191

    if (r == ROWS_TOK) {
        if (b != 0) return;
        // reduce_sim: each thread covers d = 4t..4t+3; unroll x8 for MLP
        float4 sx = make_float4(0.f, 0.f, 0.f, 0.f);
        const float4* xn = (const float4*)g_xnorm + t;
#pragma unroll
        for (int bb = 0; bb < B_; bb += 8) {
            float4 v0 = xn[(size_t)(bb + 0) * D4_];
            float4 v1 = xn[(size_t)(bb + 1) * D4_];
            float4 v2 = xn[(size_t)(bb + 2) * D4_];
            float4 v3 = xn[(size_t)(bb + 3) * D4_];
            float4 v4 = xn[(size_t)(bb + 4) * D4_];
            float4 v5 = xn[(size_t)(bb + 5) * D4_];
            float4 v6 = xn[(size_t)(bb + 6) * D4_];
            float4 v7 = xn[(size_t)(bb + 7) * D4_];
            sx.x += (v0.x + v1.x) + (v2.x + v3.x) + ((v4.x + v5.x) + (v6.x + v7.x));
            sx.y += (v0.y + v1.y) + (v2.y + v3.y) + ((v4.y + v5.y) + (v6.y + v7.y));
            sx.z += (v0.z + v1.z) + (v2.z + v3.z) + ((v4.z + v5.z) + (v6.z + v7.z));
            sx.w += (v0.w + v1.w) + (v2.w + v3.w) + ((v4.w + v5.w) + (v6.w + v7.w));
        }
        float4 kt = make_float4(0.f, 0.f, 0.f, 0.f);
#pragma unroll
        for (int p = 0; p < P_; p++) {
            float c = (float)g_cnt[p];
            float4 v = ((const float4*)g_pnorm)[(size_t)p * D4_ + t];
            kt.x += c * v.x; kt.y += c * v.y; kt.z += c * v.z; kt.w += c * v.w;
        }
        float partial = sx.x * kt.x + sx.y * kt.y + sx.z * kt.z + sx.w * kt.w;
        float tot = blk_reduce_192(partial);
        if (t == 0) out[SIM_OFF] = tot * (1.0f / (float)B_);
        return;
    }

    float4 v;
    if (r < T_ * L_) {
        v = assist[(size_t)r * D4_ + t];
    } else {
        int rr = r - T_ * L_;
        int k = rr / L_;
        int l = rr % L_;
        int idx = g_idx[b * K_ + k];
        if (idx >= 0)
            v = prompt[((size_t)idx * L_ + l) * D4_ + t];
        else
            v = make_float4(0.f, 0.f, 0.f, 0.f);
    }
    __stcs((float4*)(out + PE_OFF) + (size_t)b * ROWS_PE * D4_ + (size_t)r * D4_ + t, v);
    float* to = out + TOK_OFF + (size_t)b * ROWS_TOK * D_ + (size_t)r * D_ + (size_t)t * 4;
    __stcs(to + 0, v.x);
    __stcs(to + 1, v.y);
    __stcs(to + 2, v.z);
    __stcs(to + 3, v.w);
}

extern "C" void kernel_launch(void* const* d_in, const int* in_sizes, int n_in,
                              void* d_out, int out_size) {
    const float4* x_embed = (const float4*)d_in[0];        // [B,S,D]
    const float4* prompt = (const float4*)d_in[1];         // [P,L,D]
    const float4* prompt_key = (const float4*)d_in[2];     // [P,D]
    const float4* assist = (const float4*)d_in[3];         // [T,L,D]
    float* out = (float*)d_out;

    k_mean_copy<<<dim3(B_, Q_ + 1), D4_>>>(x_embed, prompt_key, out);
    k_xnorm_topk<<<B_, D4_>>>(out);
    k_tokens<<<dim3(ROWS_TOK + 1, B_), D4_>>>(prompt, assist, out);
}